// round 12
// baseline (speedup 1.0000x reference)
#include <cuda_runtime.h>
#include <cuda_fp16.h>
#include <cstdint>

// Problem constants
#define BS_  128
#define NE_  512
#define NQ_  128
#define EMB_ 512
#define H_   8
#define HD_  64
#define F3_  1536

// Scratch (allocation-free rule: __device__ globals)
__device__ __half g_qkv_h[(size_t)BS_ * NE_ * F3_];      // fp16 qkv
__device__ __half g_ent_h[(size_t)BS_ * NE_ * 512];      // half entities
__device__ __half g_win_h[(size_t)F3_ * 512];            // half W_in
__device__ __half g_wout_h[(size_t)EMB_ * EMB_];         // half W_out
__device__ __half g_attn_h[(size_t)BS_ * NQ_ * EMB_];    // half attention output
__device__ float  g_vd[(size_t)BS_ * NQ_ * NE_];         // valid? diff : -1
__device__ int    g_mask_i32;

// ---------------------------------------------------------------------------
// Mask dtype detection (jax bool may arrive as int32 or uint8) — warp-parallel
// ---------------------------------------------------------------------------
__global__ void detect_mask_kernel(const unsigned char* __restrict__ p) {
    int t = threadIdx.x;
    unsigned acc = 0;
    for (int g = t; g < 256; g += 32)
        acc |= (unsigned)p[4 * g + 1] | p[4 * g + 2] | p[4 * g + 3];
    unsigned any = __ballot_sync(0xFFFFFFFFu, acc != 0);
    if (t == 0) g_mask_i32 = (any == 0) ? 1 : 0;
}
__device__ __forceinline__ int mask_at(const unsigned char* __restrict__ p,
                                       int idx, int i32) {
    return (int)p[i32 ? (idx << 2) : idx];
}
__device__ __forceinline__ void valid2(const unsigned char* __restrict__ p,
                                       int idx, int i32, float& v0, float& v1) {
    if (i32) {
        int2 q = *(const int2*)(p + ((size_t)idx << 2));
        v0 = q.x ? 0.f : 1.f;
        v1 = q.y ? 0.f : 1.f;
    } else {
        unsigned short s = *(const unsigned short*)(p + idx);
        v0 = (s & 0xFF) ? 0.f : 1.f;
        v1 = (s >> 8)   ? 0.f : 1.f;
    }
}

// ---------------------------------------------------------------------------
// Fold pre_mask into diff_mask: vd = valid ? diff : -1.0  (exact fp32)
// ---------------------------------------------------------------------------
__global__ void pack_vd(const unsigned char* __restrict__ pre,
                        const float* __restrict__ diff,
                        float* __restrict__ vd, int n2) {
    const int i32 = g_mask_i32;
    for (int i = blockIdx.x * blockDim.x + threadIdx.x; i < n2;
         i += gridDim.x * blockDim.x) {
        float2 d = ((const float2*)diff)[i];
        float v0, v1;
        valid2(pre, 2 * i, i32, v0, v1);
        float2 o;
        o.x = (v0 > 0.f) ? d.x : -1.f;
        o.y = (v1 > 0.f) ? d.y : -1.f;
        ((float2*)vd)[i] = o;
    }
}

// ---------------------------------------------------------------------------
// fp32 -> fp16 bulk convert, 3 segments in one launch
// ---------------------------------------------------------------------------
__global__ void cvt_all(const float4* __restrict__ s0, uint2* __restrict__ d0, int n0,
                        const float4* __restrict__ s1, uint2* __restrict__ d1, int n1,
                        const float4* __restrict__ s2, uint2* __restrict__ d2, int n2) {
    const int total = n0 + n1 + n2;
    for (int i = blockIdx.x * blockDim.x + threadIdx.x; i < total;
         i += gridDim.x * blockDim.x) {
        const float4* s; uint2* d; int j = i;
        if (j < n0)            { s = s0; d = d0; }
        else if (j - n0 < n1)  { s = s1; d = d1; j -= n0; }
        else                   { s = s2; d = d2; j -= n0 + n1; }
        float4 v = s[j];
        __half2 a = __floats2half2_rn(v.x, v.y);
        __half2 b = __floats2half2_rn(v.z, v.w);
        uint2 o;
        o.x = *(uint32_t*)&a;
        o.y = *(uint32_t*)&b;
        d[j] = o;
    }
}

// ---------------------------------------------------------------------------
// PTX helpers
// ---------------------------------------------------------------------------
__device__ __forceinline__ uint32_t smem_u32(const void* p) {
    uint32_t a;
    asm("{ .reg .u64 t; cvta.to.shared.u64 t, %1; cvt.u32.u64 %0, t; }"
        : "=r"(a) : "l"(p));
    return a;
}
#define CP_ASYNC16(dst, src) \
    asm volatile("cp.async.cg.shared.global [%0], [%1], 16;" \
                 :: "r"(dst), "l"(src) : "memory")
#define CP_COMMIT() asm volatile("cp.async.commit_group;" ::: "memory")
#define CP_WAIT0()  asm volatile("cp.async.wait_group 0;" ::: "memory")
#define CP_WAIT1()  asm volatile("cp.async.wait_group 1;" ::: "memory")

#define LDMATRIX_X4(r0, r1, r2, r3, addr) \
    asm volatile("ldmatrix.sync.aligned.m8n8.x4.shared.b16 {%0,%1,%2,%3}, [%4];" \
                 : "=r"(r0), "=r"(r1), "=r"(r2), "=r"(r3) : "r"(addr))
#define LDMATRIX_X4_T(r0, r1, r2, r3, addr) \
    asm volatile("ldmatrix.sync.aligned.m8n8.x4.trans.shared.b16 {%0,%1,%2,%3}, [%4];" \
                 : "=r"(r0), "=r"(r1), "=r"(r2), "=r"(r3) : "r"(addr))

#define MMA_F16(d, a0, a1, a2, a3, b0, b1)                                    \
    asm volatile(                                                             \
        "mma.sync.aligned.m16n8k16.row.col.f32.f16.f16.f32 "                  \
        "{%0,%1,%2,%3}, {%4,%5,%6,%7}, {%8,%9}, {%0,%1,%2,%3};"               \
        : "+f"((d)[0]), "+f"((d)[1]), "+f"((d)[2]), "+f"((d)[3])              \
        : "r"(a0), "r"(a1), "r"(a2), "r"(a3), "r"(b0), "r"(b1))

__device__ __forceinline__ uint32_t packh2(float a, float b) {
    __half2 h = __floats2half2_rn(a, b);
    return *(uint32_t*)&h;
}

// 64B-row swizzle (GEMM tiles: 32 halves/row)
__device__ __forceinline__ uint32_t swz(int r, int c) {
    return (uint32_t)(r * 64 + ((c ^ ((r >> 1) & 3)) << 4));
}
// 128B-row swizzle (attention tiles: 64 halves/row, 8 chunks)
__device__ __forceinline__ uint32_t swz128(int r, int c) {
    return (uint32_t)(r * 128 + ((c ^ (r & 7)) << 4));
}

// ---------------------------------------------------------------------------
// fp16 tensor-core GEMM, 128x128 CTA tile, 128 threads (2x2 warps of 64x64).
// 6-buffer cp.async pipeline, ONE barrier per 2 k-iters (8 barriers total).
// Window w: issue tiles 2w+2,2w+3 (one group) -> wait_group 1 -> bar ->
// compute 2w, 2w+1. Issued buffers were last read in window w-2; window
// w-1's barrier separates that compute from this issue.
// MODE 0: merged QKV (4096 KV blocks then 512 remapped Q blocks, fp16 out).
// MODE 1: out-proj (bias + post-mask, fp32 out).
// ---------------------------------------------------------------------------
#define TBUF_B 8192                      // 128 rows * 64B (A or B)
#define GBUF_B (2 * TBUF_B)
#define GEMM_SMEM (6 * GBUF_B)           // 98304

template <int MODE>
__global__ __launch_bounds__(128, 2) void gemm_k(
    const __half* __restrict__ A, const __half* __restrict__ W,
    void* __restrict__ Cv,
    const float* __restrict__ bias, const unsigned char* __restrict__ post)
{
    extern __shared__ char smem[];
    const uint32_t sb = smem_u32(smem);
    const int tid  = threadIdx.x;
    const int lane = tid & 31;
    const int warp = tid >> 5;
    const int gid  = lane >> 2;
    const int tg   = lane & 3;
    const int wm   = warp >> 1;          // 0..1
    const int wn   = warp & 1;           // 0..1

    int bm, bn, colo, remap;
    float osc;
    const __half* B;
    int ldc;
    if (MODE == 0) {
        const int g0 = blockIdx.x;
        if (g0 < 4096) { bm = (g0 >> 3) * 128; bn = (g0 & 7) * 128;
                         B = W + 512 * 512; colo = 512; remap = 0; osc = 1.f; }
        else { const int g = g0 - 4096;
               bm = (g >> 2) * 128; bn = (g & 3) * 128;
               B = W; colo = 0; remap = 1; osc = 0.125f; }
        ldc = F3_;
    } else {
        bm = blockIdx.y * 128; bn = blockIdx.x * 128;
        B = W; colo = 0; remap = 0; osc = 1.f; ldc = EMB_;
    }

    float acc[4][8][4];
#pragma unroll
    for (int mi = 0; mi < 4; mi++)
#pragma unroll
        for (int ni = 0; ni < 8; ni++)
#pragma unroll
            for (int r = 0; r < 4; r++) acc[mi][ni][r] = 0.f;

    const int a_roff = (lane & 7) + ((lane >> 3) & 1) * 8;
    const int a_coff = lane >> 4;
    const int b_noff = (lane & 7) + (lane >> 4) * 8;
    const int b_coff = (lane >> 3) & 1;

    // copy one k-tile (A+B) into buffer (kt % 6); no commit
#define COPY1(kt) do {                                                        \
        const uint32_t ab_ = sb + ((kt) % 6) * GBUF_B;                        \
        const uint32_t bb_ = ab_ + TBUF_B;                                    \
        _Pragma("unroll")                                                     \
        for (int s = 0; s < 4; s++) {                                         \
            int idx = tid + s * 128;                                          \
            int r   = idx >> 2;                                               \
            int c   = idx & 3;                                                \
            int ga  = bm + r;                                                 \
            if (remap) ga = ((ga >> 7) << 9) | (ga & 127);                    \
            CP_ASYNC16(ab_ + swz(r, c),                                       \
                       &A[(size_t)ga * 512 + (kt) * 32 + c * 8]);             \
            CP_ASYNC16(bb_ + swz(r, c),                                       \
                       &B[(size_t)(bn + r) * 512 + (kt) * 32 + c * 8]);       \
        }                                                                     \
    } while (0)

#define COMPUTE(kt) do {                                                      \
        const uint32_t ab = sb + ((kt) % 6) * GBUF_B;                         \
        const uint32_t bb = ab + TBUF_B;                                      \
        _Pragma("unroll")                                                     \
        for (int ks = 0; ks < 2; ks++) {                                      \
            uint32_t af[4][4], bf[4][4];                                      \
            _Pragma("unroll")                                                 \
            for (int mi = 0; mi < 4; mi++)                                    \
                LDMATRIX_X4(af[mi][0], af[mi][1], af[mi][2], af[mi][3],       \
                            ab + swz(wm * 64 + mi * 16 + a_roff,              \
                                     2 * ks + a_coff));                       \
            _Pragma("unroll")                                                 \
            for (int nj = 0; nj < 4; nj++)                                    \
                LDMATRIX_X4(bf[nj][0], bf[nj][1], bf[nj][2], bf[nj][3],       \
                            bb + swz(wn * 64 + nj * 16 + b_noff,              \
                                     2 * ks + b_coff));                       \
            _Pragma("unroll")                                                 \
            for (int mi = 0; mi < 4; mi++)                                    \
                _Pragma("unroll")                                             \
                for (int nj = 0; nj < 4; nj++) {                              \
                    MMA_F16(acc[mi][2 * nj],                                  \
                            af[mi][0], af[mi][1], af[mi][2], af[mi][3],       \
                            bf[nj][0], bf[nj][1]);                            \
                    MMA_F16(acc[mi][2 * nj + 1],                              \
                            af[mi][0], af[mi][1], af[mi][2], af[mi][3],       \
                            bf[nj][2], bf[nj][3]);                            \
                }                                                             \
        }                                                                     \
    } while (0)

    // prologue: tiles 0,1 as one group
    COPY1(0); COPY1(1); CP_COMMIT();

#pragma unroll 1
    for (int kt = 0; kt < 16; kt += 2) {
        if (kt + 2 < 16) {
            COPY1(kt + 2); COPY1(kt + 3); CP_COMMIT();
            CP_WAIT1();
        } else {
            CP_WAIT0();
        }
        __syncthreads();
        COMPUTE(kt);
        COMPUTE(kt + 1);
    }
#undef COPY1
#undef COMPUTE

    const int i32 = g_mask_i32;
#pragma unroll
    for (int mi = 0; mi < 4; mi++) {
        int rbase = bm + wm * 64 + mi * 16 + gid;
#pragma unroll
        for (int hf = 0; hf < 2; hf++) {
            int row  = rbase + hf * 8;
            int grow = remap ? (((row >> 7) << 9) | (row & 127)) : row;
            float keep = 1.f;
            if (MODE == 1) keep = (mask_at(post, grow, i32) == 0) ? 1.f : 0.f;
#pragma unroll
            for (int ni = 0; ni < 8; ni++) {
                int col = bn + wn * 64 + ni * 8 + 2 * tg;
                float v0 = acc[mi][ni][hf * 2 + 0] * osc;
                float v1 = acc[mi][ni][hf * 2 + 1] * osc;
                if (MODE == 1) {
                    v0 = (v0 + bias[col])     * keep;
                    v1 = (v1 + bias[col + 1]) * keep;
                    *(float2*)&((float*)Cv)[(size_t)grow * ldc + col] =
                        make_float2(v0, v1);
                } else {
                    __half2 hv = __floats2half2_rn(v0, v1);
                    *(__half2*)&((__half*)Cv)[(size_t)grow * ldc + colo + col]
                        = hv;
                }
            }
        }
    }
}

// ---------------------------------------------------------------------------
// Fused flash-style attention on tensor cores (validated R8-R11).
// CTA = (h, b) -- h is the FAST grid axis so the 8 heads of one batch are
// co-resident and share the same vd slice through L2 (8x vd DRAM reuse).
// Q pre-scaled by 1/8. vd = valid? diff : -1. 3-stage KV pipeline.
// w_i = e_i*d_i / (T + 1e-8*S)
// ---------------------------------------------------------------------------
#define ATT_SMEM (16384 + 3 * 8192 + 3 * 8192)   // 65536

__global__ __launch_bounds__(128, 2) void attn_mma(
    const __half* __restrict__ qkvh,
    const float* __restrict__ vd,
    __half* __restrict__ attn_h)
{
    extern __shared__ char dynsm[];
    const uint32_t qsb = smem_u32(dynsm);
    const uint32_t ksb = qsb + 16384;
    const uint32_t vsb = qsb + 16384 + 3 * 8192;

    const int h    = blockIdx.x;       // fast axis: heads share vd in L2
    const int b    = blockIdx.y;
    const int tid  = threadIdx.x;
    const int lane = tid & 31;
    const int warp = tid >> 5;
    const int gid  = lane >> 2;
    const int tg   = lane & 3;

    const __half* qptr = qkvh + (size_t)b * 512 * F3_ + h * HD_;
    const __half* kptr = qptr + EMB_;
    const __half* vptr = qptr + 2 * EMB_;

    const int a_roff = (lane & 7) + ((lane >> 3) & 1) * 8;
    const int a_coff = lane >> 4;
    const int b_noff = (lane & 7) + (lane >> 4) * 8;
    const int b_coff = (lane >> 3) & 1;
    const int v_roff = lane & 15;
    const int v_coff = lane >> 4;

#define AT_ISSUE_KV(kt, buf) do {                                             \
        const uint32_t kb_ = ksb + (buf) * 8192;                              \
        const uint32_t vb_ = vsb + (buf) * 8192;                              \
        _Pragma("unroll")                                                     \
        for (int s = 0; s < 4; s++) {                                         \
            int r = (tid >> 3) + s * 16;                                      \
            int c = tid & 7;                                                  \
            size_t go = (size_t)((kt) * 64 + r) * F3_ + c * 8;                \
            CP_ASYNC16(kb_ + swz128(r, c), kptr + go);                        \
            CP_ASYNC16(vb_ + swz128(r, c), vptr + go);                        \
        }                                                                     \
        CP_COMMIT();                                                          \
    } while (0)

#pragma unroll
    for (int s = 0; s < 8; s++) {
        int r = (tid >> 3) + s * 16;
        int c = tid & 7;
        CP_ASYNC16(qsb + swz128(r, c), qptr + (size_t)r * F3_ + c * 8);
    }
    AT_ISSUE_KV(0, 0);
    AT_ISSUE_KV(1, 1);
    CP_WAIT1();
    __syncthreads();

    uint32_t qa[2][4][4];
#pragma unroll
    for (int m = 0; m < 2; m++)
#pragma unroll
        for (int ks = 0; ks < 4; ks++)
            LDMATRIX_X4(qa[m][ks][0], qa[m][ks][1], qa[m][ks][2], qa[m][ks][3],
                        qsb + swz128(warp * 32 + m * 16 + a_roff,
                                     2 * ks + a_coff));

    float oacc[2][8][4];
#pragma unroll
    for (int m = 0; m < 2; m++)
#pragma unroll
        for (int n = 0; n < 8; n++)
#pragma unroll
            for (int r = 0; r < 4; r++) oacc[m][n][r] = 0.f;
    float Ssum[2][2] = {{0.f, 0.f}, {0.f, 0.f}};
    float Tsum[2][2] = {{0.f, 0.f}, {0.f, 0.f}};

    const float* vdrow0 = vd + ((size_t)(b * NQ_ + warp * 32 + gid)) * NE_;

#pragma unroll 1
    for (int kt = 0; kt < 8; kt++) {
        const int buf = kt % 3;
        const uint32_t kb = ksb + buf * 8192;
        const uint32_t vb = vsb + buf * 8192;

        float lacc[2][8][4];
#pragma unroll
        for (int m = 0; m < 2; m++)
#pragma unroll
            for (int j = 0; j < 8; j++)
#pragma unroll
                for (int r = 0; r < 4; r++) lacc[m][j][r] = 0.f;

#pragma unroll
        for (int ks = 0; ks < 4; ks++) {
            uint32_t kf[4][4];
#pragma unroll
            for (int g = 0; g < 4; g++)
                LDMATRIX_X4(kf[g][0], kf[g][1], kf[g][2], kf[g][3],
                            kb + swz128(g * 16 + b_noff, 2 * ks + b_coff));
#pragma unroll
            for (int m = 0; m < 2; m++)
#pragma unroll
                for (int g = 0; g < 4; g++) {
                    MMA_F16(lacc[m][2 * g],
                            qa[m][ks][0], qa[m][ks][1], qa[m][ks][2], qa[m][ks][3],
                            kf[g][0], kf[g][1]);
                    MMA_F16(lacc[m][2 * g + 1],
                            qa[m][ks][0], qa[m][ks][1], qa[m][ks][2], qa[m][ks][3],
                            kf[g][2], kf[g][3]);
                }
        }

#pragma unroll
        for (int m = 0; m < 2; m++) {
            const float* vdp = vdrow0 + (size_t)m * 16 * NE_ + kt * 64 + tg * 2;
#pragma unroll
            for (int j = 0; j < 8; j++) {
                float2 d0 = *(const float2*)(vdp + j * 8);
                float2 d1 = *(const float2*)(vdp + 8 * NE_ + j * 8);
                float x0 = __expf(lacc[m][j][0]);
                float x1 = __expf(lacc[m][j][1]);
                float x2 = __expf(lacc[m][j][2]);
                float x3 = __expf(lacc[m][j][3]);
                float e0 = (d0.x >= 0.f) ? x0 : 0.f;
                float e1 = (d0.y >= 0.f) ? x1 : 0.f;
                float e2 = (d1.x >= 0.f) ? x2 : 0.f;
                float e3 = (d1.y >= 0.f) ? x3 : 0.f;
                float ed0 = x0 * fmaxf(d0.x, 0.f);
                float ed1 = x1 * fmaxf(d0.y, 0.f);
                float ed2 = x2 * fmaxf(d1.x, 0.f);
                float ed3 = x3 * fmaxf(d1.y, 0.f);
                Ssum[m][0] += e0 + e1;   Tsum[m][0] += ed0 + ed1;
                Ssum[m][1] += e2 + e3;   Tsum[m][1] += ed2 + ed3;
                lacc[m][j][0] = ed0; lacc[m][j][1] = ed1;
                lacc[m][j][2] = ed2; lacc[m][j][3] = ed3;
            }
        }

#pragma unroll
        for (int ks = 0; ks < 4; ks++) {
            uint32_t pa[2][4];
#pragma unroll
            for (int m = 0; m < 2; m++) {
                pa[m][0] = packh2(lacc[m][2 * ks][0],     lacc[m][2 * ks][1]);
                pa[m][1] = packh2(lacc[m][2 * ks][2],     lacc[m][2 * ks][3]);
                pa[m][2] = packh2(lacc[m][2 * ks + 1][0], lacc[m][2 * ks + 1][1]);
                pa[m][3] = packh2(lacc[m][2 * ks + 1][2], lacc[m][2 * ks + 1][3]);
            }
#pragma unroll
            for (int ng = 0; ng < 4; ng++) {
                uint32_t vf0, vf1, vf2, vf3;
                LDMATRIX_X4_T(vf0, vf1, vf2, vf3,
                              vb + swz128(ks * 16 + v_roff, 2 * ng + v_coff));
#pragma unroll
                for (int m = 0; m < 2; m++) {
                    MMA_F16(oacc[m][2 * ng],
                            pa[m][0], pa[m][1], pa[m][2], pa[m][3], vf0, vf1);
                    MMA_F16(oacc[m][2 * ng + 1],
                            pa[m][0], pa[m][1], pa[m][2], pa[m][3], vf2, vf3);
                }
            }
        }

        if (kt < 7) {
            if (kt + 2 < 8) { AT_ISSUE_KV(kt + 2, (kt + 2) % 3); CP_WAIT1(); }
            else            { CP_WAIT0(); }
            __syncthreads();
        }
    }
#undef AT_ISSUE_KV

#pragma unroll
    for (int m = 0; m < 2; m++)
#pragma unroll
        for (int hf = 0; hf < 2; hf++) {
            float s = Ssum[m][hf], t = Tsum[m][hf];
            s += __shfl_xor_sync(0xFFFFFFFFu, s, 1);
            s += __shfl_xor_sync(0xFFFFFFFFu, s, 2);
            t += __shfl_xor_sync(0xFFFFFFFFu, t, 1);
            t += __shfl_xor_sync(0xFFFFFFFFu, t, 2);
            float inv = (s > 0.f) ? (1.f / (t + 1e-8f * s)) : 0.f;
            const int q = warp * 32 + m * 16 + gid + hf * 8;
            __half* orow = &attn_h[((size_t)b * NQ_ + q) * EMB_ + h * HD_];
#pragma unroll
            for (int n = 0; n < 8; n++) {
                __half2 hv = __floats2half2_rn(oacc[m][n][hf * 2 + 0] * inv,
                                               oacc[m][n][hf * 2 + 1] * inv);
                *(__half2*)&orow[n * 8 + tg * 2] = hv;
            }
        }
}

// ---------------------------------------------------------------------------
// Launch
// ---------------------------------------------------------------------------
extern "C" void kernel_launch(void* const* d_in, const int* in_sizes, int n_in,
                              void* d_out, int out_size) {
    const float* entities     = (const float*)d_in[0];
    const unsigned char* pre  = (const unsigned char*)d_in[1];
    const float* diff         = (const float*)d_in[2];
    const unsigned char* post = (const unsigned char*)d_in[3];
    const float* W_in         = (const float*)d_in[4];
    const float* W_out        = (const float*)d_in[5];
    const float* b_out        = (const float*)d_in[6];
    float* out                = (float*)d_out;

    __half* qkvh   = nullptr;
    __half* ent_h  = nullptr;
    __half* win_h  = nullptr;
    __half* wout_h = nullptr;
    __half* attn_h = nullptr;
    float*  vd     = nullptr;
    cudaGetSymbolAddress((void**)&qkvh,   g_qkv_h);
    cudaGetSymbolAddress((void**)&ent_h,  g_ent_h);
    cudaGetSymbolAddress((void**)&win_h,  g_win_h);
    cudaGetSymbolAddress((void**)&wout_h, g_wout_h);
    cudaGetSymbolAddress((void**)&attn_h, g_attn_h);
    cudaGetSymbolAddress((void**)&vd,     g_vd);

    cudaFuncSetAttribute(gemm_k<0>, cudaFuncAttributeMaxDynamicSharedMemorySize,
                         GEMM_SMEM);
    cudaFuncSetAttribute(gemm_k<1>, cudaFuncAttributeMaxDynamicSharedMemorySize,
                         GEMM_SMEM);
    cudaFuncSetAttribute(attn_mma, cudaFuncAttributeMaxDynamicSharedMemorySize,
                         ATT_SMEM);

    detect_mask_kernel<<<1, 32>>>(pre);

    // fp32 -> fp16 conversions (one launch) + mask folding
    cvt_all<<<8192, 256>>>((const float4*)entities, (uint2*)ent_h,
                           (BS_ * NE_ * 512) / 4,
                           (const float4*)W_in, (uint2*)win_h,
                           (F3_ * 512) / 4,
                           (const float4*)W_out, (uint2*)wout_h,
                           (EMB_ * EMB_) / 4);
    pack_vd<<<4096, 256>>>(pre, diff, vd, (BS_ * NQ_ * NE_) / 2);

    // merged KV + Q projection (4096 KV blocks, then 512 remapped Q blocks)
    gemm_k<0><<<4608, 128, GEMM_SMEM>>>(ent_h, win_h, qkvh, nullptr, nullptr);

    // fused tensor-core attention -> half output (heads on fast grid axis)
    attn_mma<<<dim3(H_, BS_), 128, ATT_SMEM>>>(qkvh, vd, attn_h);

    // out = attn @ W_out^T + b_out, post-masked (fp32 out)
    gemm_k<1><<<dim3(4, 128), 128, GEMM_SMEM>>>(attn_h, wout_h, out,
                                                b_out, post);
}

// round 13
// speedup vs baseline: 1.0152x; 1.0152x over previous
#include <cuda_runtime.h>
#include <cuda_fp16.h>
#include <cstdint>

// Problem constants
#define BS_  128
#define NE_  512
#define NQ_  128
#define EMB_ 512
#define H_   8
#define HD_  64
#define F3_  1536

// Scratch (allocation-free rule: __device__ globals)
__device__ __half g_qkv_h[(size_t)BS_ * NE_ * F3_];      // fp16 qkv
__device__ __half g_ent_h[(size_t)BS_ * NE_ * 512];      // half entities
__device__ __half g_win_h[(size_t)F3_ * 512];            // half W_in
__device__ __half g_wout_h[(size_t)EMB_ * EMB_];         // half W_out
__device__ __half g_attn_h[(size_t)BS_ * NQ_ * EMB_];    // half attention output
__device__ float  g_vd[(size_t)BS_ * NQ_ * NE_];         // valid? diff : -1
__device__ int    g_mask_i32;

// ---------------------------------------------------------------------------
// Mask dtype detection (jax bool may arrive as int32 or uint8) — warp-parallel
// ---------------------------------------------------------------------------
__global__ void detect_mask_kernel(const unsigned char* __restrict__ p) {
    int t = threadIdx.x;
    unsigned acc = 0;
    for (int g = t; g < 256; g += 32)
        acc |= (unsigned)p[4 * g + 1] | p[4 * g + 2] | p[4 * g + 3];
    unsigned any = __ballot_sync(0xFFFFFFFFu, acc != 0);
    if (t == 0) g_mask_i32 = (any == 0) ? 1 : 0;
}
__device__ __forceinline__ int mask_at(const unsigned char* __restrict__ p,
                                       int idx, int i32) {
    return (int)p[i32 ? (idx << 2) : idx];
}
__device__ __forceinline__ void valid2(const unsigned char* __restrict__ p,
                                       int idx, int i32, float& v0, float& v1) {
    if (i32) {
        int2 q = *(const int2*)(p + ((size_t)idx << 2));
        v0 = q.x ? 0.f : 1.f;
        v1 = q.y ? 0.f : 1.f;
    } else {
        unsigned short s = *(const unsigned short*)(p + idx);
        v0 = (s & 0xFF) ? 0.f : 1.f;
        v1 = (s >> 8)   ? 0.f : 1.f;
    }
}

// ---------------------------------------------------------------------------
// Fold pre_mask into diff_mask: vd = valid ? diff : -1.0  (exact fp32)
// ---------------------------------------------------------------------------
__global__ void pack_vd(const unsigned char* __restrict__ pre,
                        const float* __restrict__ diff,
                        float* __restrict__ vd, int n2) {
    const int i32 = g_mask_i32;
    for (int i = blockIdx.x * blockDim.x + threadIdx.x; i < n2;
         i += gridDim.x * blockDim.x) {
        float2 d = ((const float2*)diff)[i];
        float v0, v1;
        valid2(pre, 2 * i, i32, v0, v1);
        float2 o;
        o.x = (v0 > 0.f) ? d.x : -1.f;
        o.y = (v1 > 0.f) ? d.y : -1.f;
        ((float2*)vd)[i] = o;
    }
}

// ---------------------------------------------------------------------------
// fp32 -> fp16 bulk convert, 3 segments in one launch
// ---------------------------------------------------------------------------
__global__ void cvt_all(const float4* __restrict__ s0, uint2* __restrict__ d0, int n0,
                        const float4* __restrict__ s1, uint2* __restrict__ d1, int n1,
                        const float4* __restrict__ s2, uint2* __restrict__ d2, int n2) {
    const int total = n0 + n1 + n2;
    for (int i = blockIdx.x * blockDim.x + threadIdx.x; i < total;
         i += gridDim.x * blockDim.x) {
        const float4* s; uint2* d; int j = i;
        if (j < n0)            { s = s0; d = d0; }
        else if (j - n0 < n1)  { s = s1; d = d1; j -= n0; }
        else                   { s = s2; d = d2; j -= n0 + n1; }
        float4 v = s[j];
        __half2 a = __floats2half2_rn(v.x, v.y);
        __half2 b = __floats2half2_rn(v.z, v.w);
        uint2 o;
        o.x = *(uint32_t*)&a;
        o.y = *(uint32_t*)&b;
        d[j] = o;
    }
}

// ---------------------------------------------------------------------------
// PTX helpers
// ---------------------------------------------------------------------------
__device__ __forceinline__ uint32_t smem_u32(const void* p) {
    uint32_t a;
    asm("{ .reg .u64 t; cvta.to.shared.u64 t, %1; cvt.u32.u64 %0, t; }"
        : "=r"(a) : "l"(p));
    return a;
}
#define CP_ASYNC16(dst, src) \
    asm volatile("cp.async.cg.shared.global [%0], [%1], 16;" \
                 :: "r"(dst), "l"(src) : "memory")
#define CP_COMMIT() asm volatile("cp.async.commit_group;" ::: "memory")
#define CP_WAIT0()  asm volatile("cp.async.wait_group 0;" ::: "memory")
#define CP_WAIT1()  asm volatile("cp.async.wait_group 1;" ::: "memory")

#define LDMATRIX_X4(r0, r1, r2, r3, addr) \
    asm volatile("ldmatrix.sync.aligned.m8n8.x4.shared.b16 {%0,%1,%2,%3}, [%4];" \
                 : "=r"(r0), "=r"(r1), "=r"(r2), "=r"(r3) : "r"(addr))
#define LDMATRIX_X4_T(r0, r1, r2, r3, addr) \
    asm volatile("ldmatrix.sync.aligned.m8n8.x4.trans.shared.b16 {%0,%1,%2,%3}, [%4];" \
                 : "=r"(r0), "=r"(r1), "=r"(r2), "=r"(r3) : "r"(addr))

#define MMA_F16(d, a0, a1, a2, a3, b0, b1)                                    \
    asm volatile(                                                             \
        "mma.sync.aligned.m16n8k16.row.col.f32.f16.f16.f32 "                  \
        "{%0,%1,%2,%3}, {%4,%5,%6,%7}, {%8,%9}, {%0,%1,%2,%3};"               \
        : "+f"((d)[0]), "+f"((d)[1]), "+f"((d)[2]), "+f"((d)[3])              \
        : "r"(a0), "r"(a1), "r"(a2), "r"(a3), "r"(b0), "r"(b1))

__device__ __forceinline__ uint32_t packh2(float a, float b) {
    __half2 h = __floats2half2_rn(a, b);
    return *(uint32_t*)&h;
}

// 64B-row swizzle (GEMM tiles: 32 halves/row)
__device__ __forceinline__ uint32_t swz(int r, int c) {
    return (uint32_t)(r * 64 + ((c ^ ((r >> 1) & 3)) << 4));
}
// 128B-row swizzle (attention tiles: 64 halves/row, 8 chunks)
__device__ __forceinline__ uint32_t swz128(int r, int c) {
    return (uint32_t)(r * 128 + ((c ^ (r & 7)) << 4));
}

// ---------------------------------------------------------------------------
// fp16 tensor-core GEMM, 128x128 CTA tile, 128 threads (2x2 warps of 64x64).
// 3-buffer cp.async pipeline (R11 scheme), one bar per k-iter.
// COMPUTE hoists ALL 16 ldmatrix of the k-tile ahead of all 64 MMAs so the
// LDSM latencies drain under the MMA stream (intra-warp pipelining).
// MODE 0: merged QKV (4096 KV blocks then 512 remapped Q blocks, fp16 out).
// MODE 1: out-proj (bias + post-mask, fp32 out).
// ---------------------------------------------------------------------------
#define TBUF_B 8192                      // 128 rows * 64B (A or B)
#define GBUF_B (2 * TBUF_B)
#define GEMM_SMEM (3 * GBUF_B)           // 49152

template <int MODE>
__global__ __launch_bounds__(128, 2) void gemm_k(
    const __half* __restrict__ A, const __half* __restrict__ W,
    void* __restrict__ Cv,
    const float* __restrict__ bias, const unsigned char* __restrict__ post)
{
    extern __shared__ char smem[];
    const uint32_t sb = smem_u32(smem);
    const int tid  = threadIdx.x;
    const int lane = tid & 31;
    const int warp = tid >> 5;
    const int gid  = lane >> 2;
    const int tg   = lane & 3;
    const int wm   = warp >> 1;          // 0..1
    const int wn   = warp & 1;           // 0..1

    int bm, bn, colo, remap;
    float osc;
    const __half* B;
    int ldc;
    if (MODE == 0) {
        const int g0 = blockIdx.x;
        if (g0 < 4096) { bm = (g0 >> 3) * 128; bn = (g0 & 7) * 128;
                         B = W + 512 * 512; colo = 512; remap = 0; osc = 1.f; }
        else { const int g = g0 - 4096;
               bm = (g >> 2) * 128; bn = (g & 3) * 128;
               B = W; colo = 0; remap = 1; osc = 0.125f; }
        ldc = F3_;
    } else {
        bm = blockIdx.y * 128; bn = blockIdx.x * 128;
        B = W; colo = 0; remap = 0; osc = 1.f; ldc = EMB_;
    }

    float acc[4][8][4];
#pragma unroll
    for (int mi = 0; mi < 4; mi++)
#pragma unroll
        for (int ni = 0; ni < 8; ni++)
#pragma unroll
            for (int r = 0; r < 4; r++) acc[mi][ni][r] = 0.f;

    const int a_roff = (lane & 7) + ((lane >> 3) & 1) * 8;
    const int a_coff = lane >> 4;
    const int b_noff = (lane & 7) + (lane >> 4) * 8;
    const int b_coff = (lane >> 3) & 1;

#define ISSUE(kt, buf) do {                                                   \
        const uint32_t ab_ = sb + (buf) * GBUF_B;                             \
        const uint32_t bb_ = ab_ + TBUF_B;                                    \
        _Pragma("unroll")                                                     \
        for (int s = 0; s < 4; s++) {                                         \
            int idx = tid + s * 128;                                          \
            int r   = idx >> 2;                                               \
            int c   = idx & 3;                                                \
            int ga  = bm + r;                                                 \
            if (remap) ga = ((ga >> 7) << 9) | (ga & 127);                    \
            CP_ASYNC16(ab_ + swz(r, c),                                       \
                       &A[(size_t)ga * 512 + (kt) * 32 + c * 8]);             \
            CP_ASYNC16(bb_ + swz(r, c),                                       \
                       &B[(size_t)(bn + r) * 512 + (kt) * 32 + c * 8]);       \
        }                                                                     \
        CP_COMMIT();                                                          \
    } while (0)

    ISSUE(0, 0);
    ISSUE(1, 1);
    CP_WAIT1();
    __syncthreads();

#pragma unroll 1
    for (int kt = 0; kt < 16; kt++) {
        const uint32_t ab = sb + (kt % 3) * GBUF_B;
        const uint32_t bb = ab + TBUF_B;

        // ---- load ALL fragments of this k-tile (both ks halves) ----
        uint32_t af[2][4][4], bf[2][4][4];
#pragma unroll
        for (int ks = 0; ks < 2; ks++) {
#pragma unroll
            for (int mi = 0; mi < 4; mi++)
                LDMATRIX_X4(af[ks][mi][0], af[ks][mi][1],
                            af[ks][mi][2], af[ks][mi][3],
                            ab + swz(wm * 64 + mi * 16 + a_roff,
                                     2 * ks + a_coff));
#pragma unroll
            for (int nj = 0; nj < 4; nj++)
                LDMATRIX_X4(bf[ks][nj][0], bf[ks][nj][1],
                            bf[ks][nj][2], bf[ks][nj][3],
                            bb + swz(wn * 64 + nj * 16 + b_noff,
                                     2 * ks + b_coff));
        }
        // ---- all 64 MMAs; early ones cover late LDSM latency ----
#pragma unroll
        for (int ks = 0; ks < 2; ks++)
#pragma unroll
            for (int mi = 0; mi < 4; mi++)
#pragma unroll
                for (int nj = 0; nj < 4; nj++) {
                    MMA_F16(acc[mi][2 * nj],
                            af[ks][mi][0], af[ks][mi][1],
                            af[ks][mi][2], af[ks][mi][3],
                            bf[ks][nj][0], bf[ks][nj][1]);
                    MMA_F16(acc[mi][2 * nj + 1],
                            af[ks][mi][0], af[ks][mi][1],
                            af[ks][mi][2], af[ks][mi][3],
                            bf[ks][nj][2], bf[ks][nj][3]);
                }

        if (kt < 15) {
            if (kt + 2 < 16) { ISSUE(kt + 2, (kt + 2) % 3); CP_WAIT1(); }
            else             { CP_WAIT0(); }
            __syncthreads();
        }
    }
#undef ISSUE

    const int i32 = g_mask_i32;
#pragma unroll
    for (int mi = 0; mi < 4; mi++) {
        int rbase = bm + wm * 64 + mi * 16 + gid;
#pragma unroll
        for (int hf = 0; hf < 2; hf++) {
            int row  = rbase + hf * 8;
            int grow = remap ? (((row >> 7) << 9) | (row & 127)) : row;
            float keep = 1.f;
            if (MODE == 1) keep = (mask_at(post, grow, i32) == 0) ? 1.f : 0.f;
#pragma unroll
            for (int ni = 0; ni < 8; ni++) {
                int col = bn + wn * 64 + ni * 8 + 2 * tg;
                float v0 = acc[mi][ni][hf * 2 + 0] * osc;
                float v1 = acc[mi][ni][hf * 2 + 1] * osc;
                if (MODE == 1) {
                    v0 = (v0 + bias[col])     * keep;
                    v1 = (v1 + bias[col + 1]) * keep;
                    *(float2*)&((float*)Cv)[(size_t)grow * ldc + col] =
                        make_float2(v0, v1);
                } else {
                    __half2 hv = __floats2half2_rn(v0, v1);
                    *(__half2*)&((__half*)Cv)[(size_t)grow * ldc + colo + col]
                        = hv;
                }
            }
        }
    }
}

// ---------------------------------------------------------------------------
// Fused flash-style attention on tensor cores (validated R8-R12).
// CTA = (h, b): h on the fast grid axis so the 8 heads of one batch are
// co-resident and share the same vd slice through L2.
// Q pre-scaled by 1/8. vd = valid? diff : -1. 3-stage KV pipeline.
// w_i = e_i*d_i / (T + 1e-8*S)
// ---------------------------------------------------------------------------
#define ATT_SMEM (16384 + 3 * 8192 + 3 * 8192)   // 65536

__global__ __launch_bounds__(128, 2) void attn_mma(
    const __half* __restrict__ qkvh,
    const float* __restrict__ vd,
    __half* __restrict__ attn_h)
{
    extern __shared__ char dynsm[];
    const uint32_t qsb = smem_u32(dynsm);
    const uint32_t ksb = qsb + 16384;
    const uint32_t vsb = qsb + 16384 + 3 * 8192;

    const int h    = blockIdx.x;       // fast axis: heads share vd in L2
    const int b    = blockIdx.y;
    const int tid  = threadIdx.x;
    const int lane = tid & 31;
    const int warp = tid >> 5;
    const int gid  = lane >> 2;
    const int tg   = lane & 3;

    const __half* qptr = qkvh + (size_t)b * 512 * F3_ + h * HD_;
    const __half* kptr = qptr + EMB_;
    const __half* vptr = qptr + 2 * EMB_;

    const int a_roff = (lane & 7) + ((lane >> 3) & 1) * 8;
    const int a_coff = lane >> 4;
    const int b_noff = (lane & 7) + (lane >> 4) * 8;
    const int b_coff = (lane >> 3) & 1;
    const int v_roff = lane & 15;
    const int v_coff = lane >> 4;

#define AT_ISSUE_KV(kt, buf) do {                                             \
        const uint32_t kb_ = ksb + (buf) * 8192;                              \
        const uint32_t vb_ = vsb + (buf) * 8192;                              \
        _Pragma("unroll")                                                     \
        for (int s = 0; s < 4; s++) {                                         \
            int r = (tid >> 3) + s * 16;                                      \
            int c = tid & 7;                                                  \
            size_t go = (size_t)((kt) * 64 + r) * F3_ + c * 8;                \
            CP_ASYNC16(kb_ + swz128(r, c), kptr + go);                        \
            CP_ASYNC16(vb_ + swz128(r, c), vptr + go);                        \
        }                                                                     \
        CP_COMMIT();                                                          \
    } while (0)

#pragma unroll
    for (int s = 0; s < 8; s++) {
        int r = (tid >> 3) + s * 16;
        int c = tid & 7;
        CP_ASYNC16(qsb + swz128(r, c), qptr + (size_t)r * F3_ + c * 8);
    }
    AT_ISSUE_KV(0, 0);
    AT_ISSUE_KV(1, 1);
    CP_WAIT1();
    __syncthreads();

    uint32_t qa[2][4][4];
#pragma unroll
    for (int m = 0; m < 2; m++)
#pragma unroll
        for (int ks = 0; ks < 4; ks++)
            LDMATRIX_X4(qa[m][ks][0], qa[m][ks][1], qa[m][ks][2], qa[m][ks][3],
                        qsb + swz128(warp * 32 + m * 16 + a_roff,
                                     2 * ks + a_coff));

    float oacc[2][8][4];
#pragma unroll
    for (int m = 0; m < 2; m++)
#pragma unroll
        for (int n = 0; n < 8; n++)
#pragma unroll
            for (int r = 0; r < 4; r++) oacc[m][n][r] = 0.f;
    float Ssum[2][2] = {{0.f, 0.f}, {0.f, 0.f}};
    float Tsum[2][2] = {{0.f, 0.f}, {0.f, 0.f}};

    const float* vdrow0 = vd + ((size_t)(b * NQ_ + warp * 32 + gid)) * NE_;

#pragma unroll 1
    for (int kt = 0; kt < 8; kt++) {
        const int buf = kt % 3;
        const uint32_t kb = ksb + buf * 8192;
        const uint32_t vb = vsb + buf * 8192;

        float lacc[2][8][4];
#pragma unroll
        for (int m = 0; m < 2; m++)
#pragma unroll
            for (int j = 0; j < 8; j++)
#pragma unroll
                for (int r = 0; r < 4; r++) lacc[m][j][r] = 0.f;

#pragma unroll
        for (int ks = 0; ks < 4; ks++) {
            uint32_t kf[4][4];
#pragma unroll
            for (int g = 0; g < 4; g++)
                LDMATRIX_X4(kf[g][0], kf[g][1], kf[g][2], kf[g][3],
                            kb + swz128(g * 16 + b_noff, 2 * ks + b_coff));
#pragma unroll
            for (int m = 0; m < 2; m++)
#pragma unroll
                for (int g = 0; g < 4; g++) {
                    MMA_F16(lacc[m][2 * g],
                            qa[m][ks][0], qa[m][ks][1], qa[m][ks][2], qa[m][ks][3],
                            kf[g][0], kf[g][1]);
                    MMA_F16(lacc[m][2 * g + 1],
                            qa[m][ks][0], qa[m][ks][1], qa[m][ks][2], qa[m][ks][3],
                            kf[g][2], kf[g][3]);
                }
        }

#pragma unroll
        for (int m = 0; m < 2; m++) {
            const float* vdp = vdrow0 + (size_t)m * 16 * NE_ + kt * 64 + tg * 2;
#pragma unroll
            for (int j = 0; j < 8; j++) {
                float2 d0 = *(const float2*)(vdp + j * 8);
                float2 d1 = *(const float2*)(vdp + 8 * NE_ + j * 8);
                float x0 = __expf(lacc[m][j][0]);
                float x1 = __expf(lacc[m][j][1]);
                float x2 = __expf(lacc[m][j][2]);
                float x3 = __expf(lacc[m][j][3]);
                float e0 = (d0.x >= 0.f) ? x0 : 0.f;
                float e1 = (d0.y >= 0.f) ? x1 : 0.f;
                float e2 = (d1.x >= 0.f) ? x2 : 0.f;
                float e3 = (d1.y >= 0.f) ? x3 : 0.f;
                float ed0 = x0 * fmaxf(d0.x, 0.f);
                float ed1 = x1 * fmaxf(d0.y, 0.f);
                float ed2 = x2 * fmaxf(d1.x, 0.f);
                float ed3 = x3 * fmaxf(d1.y, 0.f);
                Ssum[m][0] += e0 + e1;   Tsum[m][0] += ed0 + ed1;
                Ssum[m][1] += e2 + e3;   Tsum[m][1] += ed2 + ed3;
                lacc[m][j][0] = ed0; lacc[m][j][1] = ed1;
                lacc[m][j][2] = ed2; lacc[m][j][3] = ed3;
            }
        }

#pragma unroll
        for (int ks = 0; ks < 4; ks++) {
            uint32_t pa[2][4];
#pragma unroll
            for (int m = 0; m < 2; m++) {
                pa[m][0] = packh2(lacc[m][2 * ks][0],     lacc[m][2 * ks][1]);
                pa[m][1] = packh2(lacc[m][2 * ks][2],     lacc[m][2 * ks][3]);
                pa[m][2] = packh2(lacc[m][2 * ks + 1][0], lacc[m][2 * ks + 1][1]);
                pa[m][3] = packh2(lacc[m][2 * ks + 1][2], lacc[m][2 * ks + 1][3]);
            }
#pragma unroll
            for (int ng = 0; ng < 4; ng++) {
                uint32_t vf0, vf1, vf2, vf3;
                LDMATRIX_X4_T(vf0, vf1, vf2, vf3,
                              vb + swz128(ks * 16 + v_roff, 2 * ng + v_coff));
#pragma unroll
                for (int m = 0; m < 2; m++) {
                    MMA_F16(oacc[m][2 * ng],
                            pa[m][0], pa[m][1], pa[m][2], pa[m][3], vf0, vf1);
                    MMA_F16(oacc[m][2 * ng + 1],
                            pa[m][0], pa[m][1], pa[m][2], pa[m][3], vf2, vf3);
                }
            }
        }

        if (kt < 7) {
            if (kt + 2 < 8) { AT_ISSUE_KV(kt + 2, (kt + 2) % 3); CP_WAIT1(); }
            else            { CP_WAIT0(); }
            __syncthreads();
        }
    }
#undef AT_ISSUE_KV

#pragma unroll
    for (int m = 0; m < 2; m++)
#pragma unroll
        for (int hf = 0; hf < 2; hf++) {
            float s = Ssum[m][hf], t = Tsum[m][hf];
            s += __shfl_xor_sync(0xFFFFFFFFu, s, 1);
            s += __shfl_xor_sync(0xFFFFFFFFu, s, 2);
            t += __shfl_xor_sync(0xFFFFFFFFu, t, 1);
            t += __shfl_xor_sync(0xFFFFFFFFu, t, 2);
            float inv = (s > 0.f) ? (1.f / (t + 1e-8f * s)) : 0.f;
            const int q = warp * 32 + m * 16 + gid + hf * 8;
            __half* orow = &attn_h[((size_t)b * NQ_ + q) * EMB_ + h * HD_];
#pragma unroll
            for (int n = 0; n < 8; n++) {
                __half2 hv = __floats2half2_rn(oacc[m][n][hf * 2 + 0] * inv,
                                               oacc[m][n][hf * 2 + 1] * inv);
                *(__half2*)&orow[n * 8 + tg * 2] = hv;
            }
        }
}

// ---------------------------------------------------------------------------
// Launch
// ---------------------------------------------------------------------------
extern "C" void kernel_launch(void* const* d_in, const int* in_sizes, int n_in,
                              void* d_out, int out_size) {
    const float* entities     = (const float*)d_in[0];
    const unsigned char* pre  = (const unsigned char*)d_in[1];
    const float* diff         = (const float*)d_in[2];
    const unsigned char* post = (const unsigned char*)d_in[3];
    const float* W_in         = (const float*)d_in[4];
    const float* W_out        = (const float*)d_in[5];
    const float* b_out        = (const float*)d_in[6];
    float* out                = (float*)d_out;

    __half* qkvh   = nullptr;
    __half* ent_h  = nullptr;
    __half* win_h  = nullptr;
    __half* wout_h = nullptr;
    __half* attn_h = nullptr;
    float*  vd     = nullptr;
    cudaGetSymbolAddress((void**)&qkvh,   g_qkv_h);
    cudaGetSymbolAddress((void**)&ent_h,  g_ent_h);
    cudaGetSymbolAddress((void**)&win_h,  g_win_h);
    cudaGetSymbolAddress((void**)&wout_h, g_wout_h);
    cudaGetSymbolAddress((void**)&attn_h, g_attn_h);
    cudaGetSymbolAddress((void**)&vd,     g_vd);

    cudaFuncSetAttribute(gemm_k<0>, cudaFuncAttributeMaxDynamicSharedMemorySize,
                         GEMM_SMEM);
    cudaFuncSetAttribute(gemm_k<1>, cudaFuncAttributeMaxDynamicSharedMemorySize,
                         GEMM_SMEM);
    cudaFuncSetAttribute(attn_mma, cudaFuncAttributeMaxDynamicSharedMemorySize,
                         ATT_SMEM);

    detect_mask_kernel<<<1, 32>>>(pre);

    // fp32 -> fp16 conversions (one launch) + mask folding
    cvt_all<<<8192, 256>>>((const float4*)entities, (uint2*)ent_h,
                           (BS_ * NE_ * 512) / 4,
                           (const float4*)W_in, (uint2*)win_h,
                           (F3_ * 512) / 4,
                           (const float4*)W_out, (uint2*)wout_h,
                           (EMB_ * EMB_) / 4);
    pack_vd<<<4096, 256>>>(pre, diff, vd, (BS_ * NQ_ * NE_) / 2);

    // merged KV + Q projection (4096 KV blocks, then 512 remapped Q blocks)
    gemm_k<0><<<4608, 128, GEMM_SMEM>>>(ent_h, win_h, qkvh, nullptr, nullptr);

    // fused tensor-core attention -> half output (heads on fast grid axis)
    attn_mma<<<dim3(H_, BS_), 128, ATT_SMEM>>>(qkvh, vd, attn_h);

    // out = attn @ W_out^T + b_out, post-masked (fp32 out)
    gemm_k<1><<<dim3(4, 128), 128, GEMM_SMEM>>>(attn_h, wout_h, out,
                                                b_out, post);
}